// round 12
// baseline (speedup 1.0000x reference)
#include <cuda_runtime.h>
#include <stdint.h>
#include <math.h>

// Problem dims (fixed)
#define Bb 4
#define Tt 2048
#define Cc 1024
#define Hh 16
#define Dd 64
#define NC 32     // number of chunks
#define NC_SH 5
#define CL 64     // chunk length; NC*CL == Tt
#define MM (Bb*Tt)   // 8192 rows

// ---------------- scratch (device globals; no runtime alloc) ----------------
__device__ float g_xk[MM*Cc];
__device__ float g_xv[MM*Cc];
__device__ float g_xr[MM*Cc];
__device__ float g_xg[MM*Cc];
__device__ float g_r [MM*Cc];
__device__ float g_k [MM*Cc];
__device__ float g_v [MM*Cc];
__device__ float g_g [MM*Cc];
__device__ float g_z [MM*Cc];   // attn * g (tf32-rounded)
__device__ float g_y [MM*Cc];   // pre-LN output
__device__ float g_cs[Bb*Hh*NC*Dd*Dd];  // chunk-local final states
__device__ float g_ci[Bb*Hh*NC*Dd*Dd];  // chunk initial states (carry-in)
__device__ float g_wt[5*Cc*Cc];         // tf32-rounded weights (r,k,v,g,o)

__device__ __forceinline__ float tf32r(float x) {
    float y;
    asm("cvt.rna.tf32.f32 %0, %1;" : "=f"(y) : "f"(x));
    return y;
}

__device__ __forceinline__ void cp_async16(unsigned dst, const float* src) {
    asm volatile("cp.async.ca.shared.global [%0], [%1], 16;\n" :: "r"(dst), "l"(src));
}
__device__ __forceinline__ void cp_commit() {
    asm volatile("cp.async.commit_group;\n" ::);
}
__device__ __forceinline__ void cp_wait0() {
    asm volatile("cp.async.wait_group 0;\n" ::);
}
__device__ __forceinline__ void cp_wait1() {
    asm volatile("cp.async.wait_group 1;\n" ::);
}
__device__ __forceinline__ void ldsm4(unsigned &d0, unsigned &d1, unsigned &d2, unsigned &d3,
                                      unsigned addr) {
    asm volatile("ldmatrix.sync.aligned.m8n8.x4.shared.b16 {%0,%1,%2,%3}, [%4];"
                 : "=r"(d0), "=r"(d1), "=r"(d2), "=r"(d3) : "r"(addr));
}

// ---------------- kernel 0: round weights to tf32 (RNA) ----------------
__global__ __launch_bounds__(256) void roundw_kernel(
    const float* __restrict__ Wr, const float* __restrict__ Wk,
    const float* __restrict__ Wv, const float* __restrict__ Wg,
    const float* __restrict__ Wo)
{
    int idx = blockIdx.x * 256 + threadIdx.x;   // over 5*Cc*Cc/4
    const int per = Cc * Cc / 4;                 // 262144 float4 per weight
    int w = idx / per;
    int off = idx - w * per;
    const float* src = (w == 0) ? Wr : (w == 1) ? Wk : (w == 2) ? Wv : (w == 3) ? Wg : Wo;
    float4 v = ((const float4*)src)[off];
    v.x = tf32r(v.x); v.y = tf32r(v.y); v.z = tf32r(v.z); v.w = tf32r(v.w);
    ((float4*)g_wt)[idx] = v;
}

// ---------------- kernel 1: token shift + time mix (tf32-rounded out) ----------------
__global__ __launch_bounds__(256) void mix_kernel(
    const float* __restrict__ x,
    const float* __restrict__ mk, const float* __restrict__ mv,
    const float* __restrict__ mr, const float* __restrict__ mg)
{
    const int C4 = Cc / 4;
    int idx = blockIdx.x * 256 + threadIdx.x;       // over MM * C4
    int c4  = idx & (C4 - 1);
    int bt  = idx >> 8;                              // C4 == 256
    int t   = bt & (Tt - 1);
    int ts  = (t == 0) ? 1 : t - 1;
    int sidx = (bt + (ts - t)) * C4 + c4;

    const float4* x4 = (const float4*)x;
    float4 xc = x4[idx];
    float4 xs = x4[sidx];
    float4 xx = make_float4(xs.x - xc.x, xs.y - xc.y, xs.z - xc.z, xs.w - xc.w);

    float4 m;
    m = ((const float4*)mk)[c4];
    ((float4*)g_xk)[idx] = make_float4(tf32r(xc.x + xx.x*m.x), tf32r(xc.y + xx.y*m.y),
                                       tf32r(xc.z + xx.z*m.z), tf32r(xc.w + xx.w*m.w));
    m = ((const float4*)mv)[c4];
    ((float4*)g_xv)[idx] = make_float4(tf32r(xc.x + xx.x*m.x), tf32r(xc.y + xx.y*m.y),
                                       tf32r(xc.z + xx.z*m.z), tf32r(xc.w + xx.w*m.w));
    m = ((const float4*)mr)[c4];
    ((float4*)g_xr)[idx] = make_float4(tf32r(xc.x + xx.x*m.x), tf32r(xc.y + xx.y*m.y),
                                       tf32r(xc.z + xx.z*m.z), tf32r(xc.w + xx.w*m.w));
    m = ((const float4*)mg)[c4];
    ((float4*)g_xg)[idx] = make_float4(tf32r(xc.x + xx.x*m.x), tf32r(xc.y + xx.y*m.y),
                                       tf32r(xc.z + xx.z*m.z), tf32r(xc.w + xx.w*m.w));
}

// ---------------- kernel 2: TF32 tensor-core GEMM (ldmatrix + 3-stage cp.async) ----------
// C[M,N] = A[M,K] * B[N,K]^T, both K-contiguous, inputs pre-rounded to tf32.
// 256x256 block tile, BK=16, 512 threads (16 warps, 4x4), warp tile 64x64.
#define BM 256
#define BN 256
#define BK 16
#define KPAD 20   // smem row stride in floats (conflict-free LDSM: 8-row phase covers all banks)
#define NT (Cc / BK)
#define NSTAGE 3
#define SSZA (BM * KPAD * 4)       // bytes per stage, A
#define SSZBY (BN * KPAD * 4)      // bytes per stage, B
#define GEMM_SMEM (NSTAGE * (SSZA + SSZBY))

template<bool SIGMOID>
__global__ __launch_bounds__(512, 1) void gemm_tf32(
    const float* __restrict__ A, const float* __restrict__ Bw,
    float* __restrict__ Cout)
{
    extern __shared__ float dsm[];

    const int K = Cc, N = Cc;
    int tid = threadIdx.x;
    int bm = blockIdx.y * BM;
    int bn = blockIdx.x * BN;

    unsigned sA = (unsigned)__cvta_generic_to_shared(dsm);
    unsigned sB = sA + NSTAGE * SSZA;

    // cp.async mapping: thread -> row tid>>1 (0..255), float col base (tid&1)*8, two 16B chunks
    int ldrow = tid >> 1;
    int ldcol = (tid & 1) * 8;
    const float* Ag = A  + (size_t)(bm + ldrow) * K + ldcol;
    const float* Bg = Bw + (size_t)(bn + ldrow) * K + ldcol;
    unsigned dstA = sA + (unsigned)((ldrow * KPAD + ldcol) * 4);
    unsigned dstB = sB + (unsigned)((ldrow * KPAD + ldcol) * 4);

    int warp = tid >> 5, lane = tid & 31;
    int wm = (warp & 3) * 64;   // warp m offset (0..192)
    int wn = (warp >> 2) * 64;  // warp n offset (0..192)

    // ldmatrix per-thread addresses (byte offsets inside one stage)
    int lane7 = lane & 7;
    int aRow = lane7 + ((lane >> 3) & 1) * 8;   // 0..15 within 16-row mt tile
    int aCol = ((lane >> 4) & 1) * 4;           // 0 or 4 (k offset)
    int bRow = lane7 + ((lane >> 4) & 1) * 8;   // 0..15 within 16-row nt pair
    int bCol = ((lane >> 3) & 1) * 4;
    unsigned aAddr = sA + (unsigned)(((wm + aRow) * KPAD + aCol) * 4);
    unsigned bAddr = sB + (unsigned)(((wn + bRow) * KPAD + bCol) * 4);

    float acc[4][8][4];
    #pragma unroll
    for (int i = 0; i < 4; i++)
        #pragma unroll
        for (int j = 0; j < 8; j++)
            #pragma unroll
            for (int r = 0; r < 4; r++) acc[i][j][r] = 0.f;

    // prologue: stages 0 and 1
    #pragma unroll
    for (int p = 0; p < 2; p++) {
        cp_async16(dstA + p * SSZA, Ag + p * BK);
        cp_async16(dstA + p * SSZA + 16, Ag + p * BK + 4);
        cp_async16(dstB + p * SSZBY, Bg + p * BK);
        cp_async16(dstB + p * SSZBY + 16, Bg + p * BK + 4);
        cp_commit();
    }

    int s = 0;
    for (int t = 0; t < NT; t++) {
        if (t == NT - 1) cp_wait0(); else cp_wait1();
        __syncthreads();

        if (t + 2 < NT) {
            int sp = (s == 0) ? 2 : s - 1;          // (t+2) % 3
            int k0 = (t + 2) * BK;
            cp_async16(dstA + sp * SSZA, Ag + k0);
            cp_async16(dstA + sp * SSZA + 16, Ag + k0 + 4);
            cp_async16(dstB + sp * SSZBY, Bg + k0);
            cp_async16(dstB + sp * SSZBY + 16, Bg + k0 + 4);
            cp_commit();
        }

        unsigned aS = aAddr + (unsigned)(s * SSZA);
        unsigned bS = bAddr + (unsigned)(s * SSZBY);

        #pragma unroll
        for (int kk = 0; kk < BK; kk += 8) {
            unsigned afr[4][4];
            unsigned bfr[8][2];
            #pragma unroll
            for (int mt = 0; mt < 4; mt++)
                ldsm4(afr[mt][0], afr[mt][1], afr[mt][2], afr[mt][3],
                      aS + (unsigned)((mt * 16 * KPAD + kk) * 4));
            #pragma unroll
            for (int p = 0; p < 4; p++)
                ldsm4(bfr[2*p][0], bfr[2*p][1], bfr[2*p+1][0], bfr[2*p+1][1],
                      bS + (unsigned)((p * 16 * KPAD + kk) * 4));
            #pragma unroll
            for (int mt = 0; mt < 4; mt++)
                #pragma unroll
                for (int nt = 0; nt < 8; nt++) {
                    asm volatile(
                        "mma.sync.aligned.m16n8k8.row.col.f32.tf32.tf32.f32 "
                        "{%0,%1,%2,%3}, {%4,%5,%6,%7}, {%8,%9}, {%0,%1,%2,%3};"
                        : "+f"(acc[mt][nt][0]), "+f"(acc[mt][nt][1]),
                          "+f"(acc[mt][nt][2]), "+f"(acc[mt][nt][3])
                        : "r"(afr[mt][0]), "r"(afr[mt][1]), "r"(afr[mt][2]), "r"(afr[mt][3]),
                          "r"(bfr[nt][0]), "r"(bfr[nt][1]));
                }
        }
        s = (s == 2) ? 0 : s + 1;
    }

    // epilogue: c0/c1 at (row=group, col=2*tg), c2/c3 at (row+8, col)
    int group = lane >> 2;
    int tg = lane & 3;
    #pragma unroll
    for (int mt = 0; mt < 4; mt++) {
        int row0 = bm + wm + mt * 16 + group;
        #pragma unroll
        for (int nt = 0; nt < 8; nt++) {
            int col = bn + wn + nt * 8 + 2 * tg;
            float v0 = acc[mt][nt][0], v1 = acc[mt][nt][1];
            float v2 = acc[mt][nt][2], v3 = acc[mt][nt][3];
            if (SIGMOID) {
                v0 = 1.f / (1.f + expf(-v0));
                v1 = 1.f / (1.f + expf(-v1));
                v2 = 1.f / (1.f + expf(-v2));
                v3 = 1.f / (1.f + expf(-v3));
            }
            *(float2*)(Cout + (size_t)row0 * N + col)       = make_float2(v0, v1);
            *(float2*)(Cout + (size_t)(row0 + 8) * N + col) = make_float2(v2, v3);
        }
    }
}

// ---------------- kernel 3a: chunk-local states (tile-prefetched) ----------------
#define TS_ST 32
__global__ __launch_bounds__(256) void scan_state_kernel(const float* __restrict__ decay)
{
    int blk = blockIdx.x;           // bh*NC + c
    int c  = blk & (NC - 1);
    int bh = blk >> NC_SH;
    int b  = bh >> 4, h = bh & (Hh - 1);
    int tid = threadIdx.x;
    int i = tid >> 2, q = tid & 3;

    float w = expf(-expf(decay[h * Dd + i]));

    __shared__ float sk[2][TS_ST][Dd];
    __shared__ float sv[2][TS_ST][Dd];
    unsigned skb = (unsigned)__cvta_generic_to_shared(&sk[0][0][0]);
    unsigned svb = (unsigned)__cvta_generic_to_shared(&sv[0][0][0]);

    float s[16];
    #pragma unroll
    for (int j = 0; j < 16; j++) s[j] = 0.f;

    int base = (b * Tt + c * CL) * Cc + h * Dd;

    // tile loader: 32 steps * 16 float4-groups = 512 slots, 2 per thread
    #define LOAD_ST(bufi, t0) do { \
        _Pragma("unroll") \
        for (int j = 0; j < 2; j++) { \
            int idx = tid + j * 256; \
            int tl = idx >> 4, grp = (idx & 15) << 2; \
            int go = base + ((t0) + tl) * Cc + grp; \
            unsigned so = (unsigned)((((bufi) * TS_ST + tl) * Dd + grp) * 4); \
            cp_async16(skb + so, g_k + go); \
            cp_async16(svb + so, g_v + go); \
        } cp_commit(); } while (0)

    LOAD_ST(0, 0);
    for (int tile = 0; tile < CL / TS_ST; tile++) {
        cp_wait0();
        __syncthreads();
        if (tile + 1 < CL / TS_ST) LOAD_ST((tile + 1) & 1, (tile + 1) * TS_ST);
        int buf = tile & 1;
        #pragma unroll 4
        for (int tl = 0; tl < TS_ST; tl++) {
            float ki = sk[buf][tl][i];
            const float4* vv = (const float4*)&sv[buf][tl][q * 16];
            #pragma unroll
            for (int jj = 0; jj < 4; jj++) {
                float4 v4 = vv[jj];
                s[jj*4+0] = fmaf(s[jj*4+0], w, ki * v4.x);
                s[jj*4+1] = fmaf(s[jj*4+1], w, ki * v4.y);
                s[jj*4+2] = fmaf(s[jj*4+2], w, ki * v4.z);
                s[jj*4+3] = fmaf(s[jj*4+3], w, ki * v4.w);
            }
        }
    }
    #undef LOAD_ST

    float* dst = g_cs + blk * (Dd * Dd) + i * Dd + q * 16;
    #pragma unroll
    for (int jj = 0; jj < 4; jj++)
        ((float4*)dst)[jj] = make_float4(s[jj*4], s[jj*4+1], s[jj*4+2], s[jj*4+3]);
}

// ---------------- kernel 3b: prefix combine over chunks ----------------
__global__ __launch_bounds__(256) void combine_kernel(const float* __restrict__ decay)
{
    int bh = blockIdx.x;
    int h = bh & (Hh - 1);
    int tid = threadIdx.x;
    int i = tid >> 2, q = tid & 3;

    float w = expf(-expf(decay[h * Dd + i]));
    float wL = w;
    #pragma unroll
    for (int p = 0; p < 6; p++) wL *= wL;   // w^64 (CL = 64)

    float s[16];
    #pragma unroll
    for (int j = 0; j < 16; j++) s[j] = 0.f;

    for (int c = 0; c < NC; c++) {
        int off = (bh * NC + c) * (Dd * Dd) + i * Dd + q * 16;
        float4* dsti = (float4*)(g_ci + off);
        const float4* src = (const float4*)(g_cs + off);
        #pragma unroll
        for (int jj = 0; jj < 4; jj++) {
            dsti[jj] = make_float4(s[jj*4], s[jj*4+1], s[jj*4+2], s[jj*4+3]);
            float4 c4 = src[jj];
            s[jj*4+0] = fmaf(s[jj*4+0], wL, c4.x);
            s[jj*4+1] = fmaf(s[jj*4+1], wL, c4.y);
            s[jj*4+2] = fmaf(s[jj*4+2], wL, c4.z);
            s[jj*4+3] = fmaf(s[jj*4+3], wL, c4.w);
        }
    }
}

// ---------------- kernel 3c: outputs with carry-in, fused gating (tile-prefetched) ---
#define TS_OT 16
__global__ __launch_bounds__(256) void scan_out_kernel(const float* __restrict__ decay)
{
    int blk = blockIdx.x;
    int c  = blk & (NC - 1);
    int bh = blk >> NC_SH;
    int b  = bh >> 4, h = bh & (Hh - 1);
    int tid = threadIdx.x;
    int i = tid >> 2, q = tid & 3;

    float w = expf(-expf(decay[h * Dd + i]));

    // [buf][tensor 0=k,1=v,2=r,3=g][tl][d]
    __shared__ float sh[2][4][TS_OT][Dd];
    unsigned shb = (unsigned)__cvta_generic_to_shared(&sh[0][0][0][0]);

    float s[16];
    {
        const float4* src = (const float4*)(g_ci + blk * (Dd * Dd) + i * Dd + q * 16);
        #pragma unroll
        for (int jj = 0; jj < 4; jj++) {
            float4 t4 = src[jj];
            s[jj*4+0] = t4.x; s[jj*4+1] = t4.y; s[jj*4+2] = t4.z; s[jj*4+3] = t4.w;
        }
    }

    int base = (b * Tt + c * CL) * Cc + h * Dd;

    // tile loader: 4 tensors * 16 steps * 16 groups = 1024 slots, 4 per thread
    #define LOAD_OT(bufi, t0) do { \
        _Pragma("unroll") \
        for (int j = 0; j < 4; j++) { \
            int idx = tid + j * 256; \
            int tn = idx >> 8; \
            int tl = (idx >> 4) & 15; \
            int grp = (idx & 15) << 2; \
            const float* src = (tn == 0) ? g_k : (tn == 1) ? g_v : (tn == 2) ? g_r : g_g; \
            int go = base + ((t0) + tl) * Cc + grp; \
            unsigned so = (unsigned)(((((bufi) * 4 + tn) * TS_OT + tl) * Dd + grp) * 4); \
            cp_async16(shb + so, src + go); \
        } cp_commit(); } while (0)

    LOAD_OT(0, 0);
    for (int tile = 0; tile < CL / TS_OT; tile++) {
        cp_wait0();
        __syncthreads();
        if (tile + 1 < CL / TS_OT) LOAD_OT((tile + 1) & 1, (tile + 1) * TS_OT);
        int buf = tile & 1;
        #pragma unroll 2
        for (int tl = 0; tl < TS_OT; tl++) {
            float ki = sh[buf][0][tl][i];
            const float4* vv = (const float4*)&sh[buf][1][tl][q * 16];
            const float4* rr = (const float4*)&sh[buf][2][tl][q * 16];
            float a0 = 0.f, a1 = 0.f, a2 = 0.f, a3 = 0.f;
            {
                float4 v4, r4;
                v4 = vv[0]; r4 = rr[0];
                s[0] = fmaf(s[0], w, ki*v4.x); a0 = fmaf(s[0], r4.x, a0);
                s[1] = fmaf(s[1], w, ki*v4.y); a0 = fmaf(s[1], r4.y, a0);
                s[2] = fmaf(s[2], w, ki*v4.z); a0 = fmaf(s[2], r4.z, a0);
                s[3] = fmaf(s[3], w, ki*v4.w); a0 = fmaf(s[3], r4.w, a0);
                v4 = vv[1]; r4 = rr[1];
                s[4] = fmaf(s[4], w, ki*v4.x); a1 = fmaf(s[4], r4.x, a1);
                s[5] = fmaf(s[5], w, ki*v4.y); a1 = fmaf(s[5], r4.y, a1);
                s[6] = fmaf(s[6], w, ki*v4.z); a1 = fmaf(s[6], r4.z, a1);
                s[7] = fmaf(s[7], w, ki*v4.w); a1 = fmaf(s[7], r4.w, a1);
                v4 = vv[2]; r4 = rr[2];
                s[8]  = fmaf(s[8],  w, ki*v4.x); a2 = fmaf(s[8],  r4.x, a2);
                s[9]  = fmaf(s[9],  w, ki*v4.y); a2 = fmaf(s[9],  r4.y, a2);
                s[10] = fmaf(s[10], w, ki*v4.z); a2 = fmaf(s[10], r4.z, a2);
                s[11] = fmaf(s[11], w, ki*v4.w); a2 = fmaf(s[11], r4.w, a2);
                v4 = vv[3]; r4 = rr[3];
                s[12] = fmaf(s[12], w, ki*v4.x); a3 = fmaf(s[12], r4.x, a3);
                s[13] = fmaf(s[13], w, ki*v4.y); a3 = fmaf(s[13], r4.y, a3);
                s[14] = fmaf(s[14], w, ki*v4.z); a3 = fmaf(s[14], r4.z, a3);
                s[15] = fmaf(s[15], w, ki*v4.w); a3 = fmaf(s[15], r4.w, a3);
            }
            float acc = (a0 + a1) + (a2 + a3);
            acc += __shfl_xor_sync(0xffffffffu, acc, 1);
            acc += __shfl_xor_sync(0xffffffffu, acc, 2);
            if (q == 0)
                g_z[base + (tile * TS_OT + tl) * Cc + i] = tf32r(acc * sh[buf][3][tl][i]);
        }
    }
    #undef LOAD_OT
}

// ---------------- kernel 4: LayerNorm ----------------
__global__ __launch_bounds__(256) void ln_kernel(
    const float* __restrict__ gamma, const float* __restrict__ beta,
    float* __restrict__ out)
{
    int row = blockIdx.x;
    int tid = threadIdx.x;
    const float4* yr = (const float4*)(g_y + (size_t)row * Cc);
    float4 v = yr[tid];
    float sum = v.x + v.y + v.z + v.w;
    float sq  = v.x*v.x + v.y*v.y + v.z*v.z + v.w*v.w;
    #pragma unroll
    for (int o = 16; o; o >>= 1) {
        sum += __shfl_xor_sync(0xffffffffu, sum, o);
        sq  += __shfl_xor_sync(0xffffffffu, sq,  o);
    }
    __shared__ float ssum[8], ssq[8];
    int wid = tid >> 5, lid = tid & 31;
    if (lid == 0) { ssum[wid] = sum; ssq[wid] = sq; }
    __syncthreads();
    if (tid == 0) {
        float S = 0.f, Q = 0.f;
        #pragma unroll
        for (int k = 0; k < 8; k++) { S += ssum[k]; Q += ssq[k]; }
        ssum[0] = S; ssq[0] = Q;
    }
    __syncthreads();
    float mu  = ssum[0] * (1.f / Cc);
    float var = ssq[0] * (1.f / Cc) - mu * mu;
    float rstd = rsqrtf(var + 1e-5f);
    float4 ga = ((const float4*)gamma)[tid];
    float4 be = ((const float4*)beta)[tid];
    float4 o;
    o.x = (v.x - mu) * rstd * ga.x + be.x;
    o.y = (v.y - mu) * rstd * ga.y + be.y;
    o.z = (v.z - mu) * rstd * ga.z + be.z;
    o.w = (v.w - mu) * rstd * ga.w + be.w;
    ((float4*)out)[(size_t)row * (Cc / 4) + tid] = o;
}

// ---------------- launch ----------------
extern "C" void kernel_launch(void* const* d_in, const int* in_sizes, int n_in,
                              void* d_out, int out_size)
{
    const float* x   = (const float*)d_in[0];
    const float* dec = (const float*)d_in[1];
    const float* mk  = (const float*)d_in[2];
    const float* mv  = (const float*)d_in[3];
    const float* mr  = (const float*)d_in[4];
    const float* mg  = (const float*)d_in[5];
    const float* Wr  = (const float*)d_in[6];
    const float* Wk  = (const float*)d_in[7];
    const float* Wv  = (const float*)d_in[8];
    const float* Wg  = (const float*)d_in[9];
    const float* Wo  = (const float*)d_in[10];
    const float* ga  = (const float*)d_in[11];
    const float* be  = (const float*)d_in[12];
    float* out = (float*)d_out;

    float *xk, *xv, *xr, *xg, *pr, *pk, *pv, *pg, *pz, *py, *wt;
    cudaGetSymbolAddress((void**)&xk, g_xk);
    cudaGetSymbolAddress((void**)&xv, g_xv);
    cudaGetSymbolAddress((void**)&xr, g_xr);
    cudaGetSymbolAddress((void**)&xg, g_xg);
    cudaGetSymbolAddress((void**)&pr, g_r);
    cudaGetSymbolAddress((void**)&pk, g_k);
    cudaGetSymbolAddress((void**)&pv, g_v);
    cudaGetSymbolAddress((void**)&pg, g_g);
    cudaGetSymbolAddress((void**)&pz, g_z);
    cudaGetSymbolAddress((void**)&py, g_y);
    cudaGetSymbolAddress((void**)&wt, g_wt);

    // opt-in dynamic smem for the GEMM (no allocation; idempotent)
    cudaFuncSetAttribute(gemm_tf32<false>, cudaFuncAttributeMaxDynamicSharedMemorySize, GEMM_SMEM);
    cudaFuncSetAttribute(gemm_tf32<true>,  cudaFuncAttributeMaxDynamicSharedMemorySize, GEMM_SMEM);

    roundw_kernel<<<5 * Cc * Cc / 4 / 256, 256>>>(Wr, Wk, Wv, Wg, Wo);
    mix_kernel<<<MM * (Cc / 4) / 256, 256>>>(x, mk, mv, mr, mg);

    dim3 gg(Cc / BN, MM / BM);   // (4, 32)
    const int WSZ = Cc * Cc;
    gemm_tf32<false><<<gg, 512, GEMM_SMEM>>>(xr, wt + 0 * WSZ, pr);
    gemm_tf32<false><<<gg, 512, GEMM_SMEM>>>(xk, wt + 1 * WSZ, pk);
    gemm_tf32<false><<<gg, 512, GEMM_SMEM>>>(xv, wt + 2 * WSZ, pv);
    gemm_tf32<true ><<<gg, 512, GEMM_SMEM>>>(xg, wt + 3 * WSZ, pg);

    scan_state_kernel<<<Bb * Hh * NC, 256>>>(dec);
    combine_kernel<<<Bb * Hh, 256>>>(dec);
    scan_out_kernel<<<Bb * Hh * NC, 256>>>(dec);

    gemm_tf32<false><<<gg, 512, GEMM_SMEM>>>(pz, wt + 4 * WSZ, py);

    ln_kernel<<<MM, 256>>>(ga, be, out);
}

// round 14
// speedup vs baseline: 1.7616x; 1.7616x over previous
#include <cuda_runtime.h>
#include <stdint.h>
#include <math.h>

// Problem dims (fixed)
#define Bb 4
#define Tt 2048
#define Cc 1024
#define Hh 16
#define Dd 64
#define NC 32     // number of chunks
#define NC_SH 5
#define CL 64     // chunk length; NC*CL == Tt
#define MM (Bb*Tt)   // 8192 rows

// ---------------- scratch (device globals; no runtime alloc) ----------------
__device__ float g_xk[MM*Cc];
__device__ float g_xv[MM*Cc];
__device__ float g_xr[MM*Cc];
__device__ float g_xg[MM*Cc];
__device__ float g_r [MM*Cc];
__device__ float g_k [MM*Cc];
__device__ float g_v [MM*Cc];
__device__ float g_g [MM*Cc];
__device__ float g_z [MM*Cc];   // attn * g (tf32-rounded)
__device__ float g_y [MM*Cc];   // pre-LN output
__device__ float g_cs[Bb*Hh*NC*Dd*Dd];  // chunk-local final states
__device__ float g_ci[Bb*Hh*NC*Dd*Dd];  // chunk initial states (carry-in)
__device__ float g_wt[5*Cc*Cc];         // tf32-rounded weights (r,k,v,g,o)

__device__ __forceinline__ float tf32r(float x) {
    float y;
    asm("cvt.rna.tf32.f32 %0, %1;" : "=f"(y) : "f"(x));
    return y;
}

__device__ __forceinline__ void cp_async16(unsigned dst, const float* src) {
    asm volatile("cp.async.ca.shared.global [%0], [%1], 16;\n" :: "r"(dst), "l"(src));
}
__device__ __forceinline__ void cp_commit() {
    asm volatile("cp.async.commit_group;\n" ::);
}
__device__ __forceinline__ void cp_wait0() {
    asm volatile("cp.async.wait_group 0;\n" ::);
}
__device__ __forceinline__ void cp_wait1() {
    asm volatile("cp.async.wait_group 1;\n" ::);
}
__device__ __forceinline__ void ldsm4(unsigned &d0, unsigned &d1, unsigned &d2, unsigned &d3,
                                      unsigned addr) {
    asm volatile("ldmatrix.sync.aligned.m8n8.x4.shared.b16 {%0,%1,%2,%3}, [%4];"
                 : "=r"(d0), "=r"(d1), "=r"(d2), "=r"(d3) : "r"(addr));
}

// ---------------- kernel 0: round weights to tf32 (RNA) ----------------
__global__ __launch_bounds__(256) void roundw_kernel(
    const float* __restrict__ Wr, const float* __restrict__ Wk,
    const float* __restrict__ Wv, const float* __restrict__ Wg,
    const float* __restrict__ Wo)
{
    int idx = blockIdx.x * 256 + threadIdx.x;   // over 5*Cc*Cc/4
    const int per = Cc * Cc / 4;                 // 262144 float4 per weight
    int w = idx / per;
    int off = idx - w * per;
    const float* src = (w == 0) ? Wr : (w == 1) ? Wk : (w == 2) ? Wv : (w == 3) ? Wg : Wo;
    float4 v = ((const float4*)src)[off];
    v.x = tf32r(v.x); v.y = tf32r(v.y); v.z = tf32r(v.z); v.w = tf32r(v.w);
    ((float4*)g_wt)[idx] = v;
}

// ---------------- kernel 1: token shift + time mix (tf32-rounded out) ----------------
__global__ __launch_bounds__(256) void mix_kernel(
    const float* __restrict__ x,
    const float* __restrict__ mk, const float* __restrict__ mv,
    const float* __restrict__ mr, const float* __restrict__ mg)
{
    const int C4 = Cc / 4;
    int idx = blockIdx.x * 256 + threadIdx.x;       // over MM * C4
    int c4  = idx & (C4 - 1);
    int bt  = idx >> 8;                              // C4 == 256
    int t   = bt & (Tt - 1);
    int ts  = (t == 0) ? 1 : t - 1;
    int sidx = (bt + (ts - t)) * C4 + c4;

    const float4* x4 = (const float4*)x;
    float4 xc = x4[idx];
    float4 xs = x4[sidx];
    float4 xx = make_float4(xs.x - xc.x, xs.y - xc.y, xs.z - xc.z, xs.w - xc.w);

    float4 m;
    m = ((const float4*)mk)[c4];
    ((float4*)g_xk)[idx] = make_float4(tf32r(xc.x + xx.x*m.x), tf32r(xc.y + xx.y*m.y),
                                       tf32r(xc.z + xx.z*m.z), tf32r(xc.w + xx.w*m.w));
    m = ((const float4*)mv)[c4];
    ((float4*)g_xv)[idx] = make_float4(tf32r(xc.x + xx.x*m.x), tf32r(xc.y + xx.y*m.y),
                                       tf32r(xc.z + xx.z*m.z), tf32r(xc.w + xx.w*m.w));
    m = ((const float4*)mr)[c4];
    ((float4*)g_xr)[idx] = make_float4(tf32r(xc.x + xx.x*m.x), tf32r(xc.y + xx.y*m.y),
                                       tf32r(xc.z + xx.z*m.z), tf32r(xc.w + xx.w*m.w));
    m = ((const float4*)mg)[c4];
    ((float4*)g_xg)[idx] = make_float4(tf32r(xc.x + xx.x*m.x), tf32r(xc.y + xx.y*m.y),
                                       tf32r(xc.z + xx.z*m.z), tf32r(xc.w + xx.w*m.w));
}

// ---------------- kernel 2: TF32 tensor-core GEMM (ldmatrix + 3-stage cp.async) ----------
// C[M,N] = A[M,K] * B[N,K]^T, both K-contiguous, inputs pre-rounded to tf32.
// 256x128 block tile, BK=16, 512 threads (16 warps, 4 m x 4 n), warp tile 64x32.
#define BM 256
#define BN 128
#define BK 16
#define KPAD 20   // smem row stride in floats (conflict-free LDSM: 8-row phase covers all banks)
#define NT (Cc / BK)
#define NSTAGE 3
#define SSZA (BM * KPAD * 4)       // bytes per stage, A
#define SSZBY (BN * KPAD * 4)      // bytes per stage, B
#define GEMM_SMEM (NSTAGE * (SSZA + SSZBY))

template<bool SIGMOID>
__global__ __launch_bounds__(512, 1) void gemm_tf32(
    const float* __restrict__ A, const float* __restrict__ Bw,
    float* __restrict__ Cout)
{
    extern __shared__ float dsm[];

    const int K = Cc, N = Cc;
    int tid = threadIdx.x;
    int bm = blockIdx.y * BM;
    int bn = blockIdx.x * BN;

    unsigned sA = (unsigned)__cvta_generic_to_shared(dsm);
    unsigned sB = sA + NSTAGE * SSZA;

    // cp.async mapping:
    //  A: thread -> row tid>>1 (0..255), col (tid&1)*8 floats, two 16B chunks
    //  B: thread -> row tid>>2 (0..127), col (tid&3)*4 floats, one 16B chunk
    int arow = tid >> 1;
    int acol = (tid & 1) * 8;
    int brow = tid >> 2;
    int bcol = (tid & 3) * 4;
    const float* Ag = A  + (size_t)(bm + arow) * K + acol;
    const float* Bg = Bw + (size_t)(bn + brow) * K + bcol;
    unsigned dstA = sA + (unsigned)((arow * KPAD + acol) * 4);
    unsigned dstB = sB + (unsigned)((brow * KPAD + bcol) * 4);

    int warp = tid >> 5, lane = tid & 31;
    int wm = (warp & 3) * 64;   // warp m offset (0..192)
    int wn = (warp >> 2) * 32;  // warp n offset (0..96)

    // ldmatrix per-thread addresses (byte offsets inside one stage)
    int lane7 = lane & 7;
    int aRow = lane7 + ((lane >> 3) & 1) * 8;   // 0..15 within 16-row mt tile
    int aCol = ((lane >> 4) & 1) * 4;           // 0 or 4 (k offset)
    int bRow = lane7 + ((lane >> 4) & 1) * 8;   // 0..15 within 16-row nt pair
    int bCol = ((lane >> 3) & 1) * 4;
    unsigned aAddr = sA + (unsigned)(((wm + aRow) * KPAD + aCol) * 4);
    unsigned bAddr = sB + (unsigned)(((wn + bRow) * KPAD + bCol) * 4);

    float acc[4][4][4];
    #pragma unroll
    for (int i = 0; i < 4; i++)
        #pragma unroll
        for (int j = 0; j < 4; j++)
            #pragma unroll
            for (int r = 0; r < 4; r++) acc[i][j][r] = 0.f;

    // prologue: stages 0 and 1
    #pragma unroll
    for (int p = 0; p < 2; p++) {
        cp_async16(dstA + p * SSZA, Ag + p * BK);
        cp_async16(dstA + p * SSZA + 16, Ag + p * BK + 4);
        cp_async16(dstB + p * SSZBY, Bg + p * BK);
        cp_commit();
    }

    int s = 0;
    for (int t = 0; t < NT; t++) {
        if (t == NT - 1) cp_wait0(); else cp_wait1();
        __syncthreads();

        if (t + 2 < NT) {
            int sp = (s == 0) ? 2 : s - 1;          // (t+2) % 3
            int k0 = (t + 2) * BK;
            cp_async16(dstA + sp * SSZA, Ag + k0);
            cp_async16(dstA + sp * SSZA + 16, Ag + k0 + 4);
            cp_async16(dstB + sp * SSZBY, Bg + k0);
            cp_commit();
        }

        unsigned aS = aAddr + (unsigned)(s * SSZA);
        unsigned bS = bAddr + (unsigned)(s * SSZBY);

        #pragma unroll
        for (int kk = 0; kk < BK; kk += 8) {
            unsigned afr[4][4];
            unsigned bfr[4][2];
            #pragma unroll
            for (int mt = 0; mt < 4; mt++)
                ldsm4(afr[mt][0], afr[mt][1], afr[mt][2], afr[mt][3],
                      aS + (unsigned)((mt * 16 * KPAD + kk) * 4));
            #pragma unroll
            for (int p = 0; p < 2; p++)
                ldsm4(bfr[2*p][0], bfr[2*p][1], bfr[2*p+1][0], bfr[2*p+1][1],
                      bS + (unsigned)((p * 16 * KPAD + kk) * 4));
            #pragma unroll
            for (int mt = 0; mt < 4; mt++)
                #pragma unroll
                for (int nt = 0; nt < 4; nt++) {
                    asm volatile(
                        "mma.sync.aligned.m16n8k8.row.col.f32.tf32.tf32.f32 "
                        "{%0,%1,%2,%3}, {%4,%5,%6,%7}, {%8,%9}, {%0,%1,%2,%3};"
                        : "+f"(acc[mt][nt][0]), "+f"(acc[mt][nt][1]),
                          "+f"(acc[mt][nt][2]), "+f"(acc[mt][nt][3])
                        : "r"(afr[mt][0]), "r"(afr[mt][1]), "r"(afr[mt][2]), "r"(afr[mt][3]),
                          "r"(bfr[nt][0]), "r"(bfr[nt][1]));
                }
        }
        s = (s == 2) ? 0 : s + 1;
    }

    // epilogue: c0/c1 at (row=group, col=2*tg), c2/c3 at (row+8, col)
    int group = lane >> 2;
    int tg = lane & 3;
    #pragma unroll
    for (int mt = 0; mt < 4; mt++) {
        int row0 = bm + wm + mt * 16 + group;
        #pragma unroll
        for (int nt = 0; nt < 4; nt++) {
            int col = bn + wn + nt * 8 + 2 * tg;
            float v0 = acc[mt][nt][0], v1 = acc[mt][nt][1];
            float v2 = acc[mt][nt][2], v3 = acc[mt][nt][3];
            if (SIGMOID) {
                v0 = 1.f / (1.f + expf(-v0));
                v1 = 1.f / (1.f + expf(-v1));
                v2 = 1.f / (1.f + expf(-v2));
                v3 = 1.f / (1.f + expf(-v3));
            }
            *(float2*)(Cout + (size_t)row0 * N + col)       = make_float2(v0, v1);
            *(float2*)(Cout + (size_t)(row0 + 8) * N + col) = make_float2(v2, v3);
        }
    }
}

// ---------------- kernel 3a: chunk-local states (tile-prefetched) ----------------
#define TS_ST 32
__global__ __launch_bounds__(256) void scan_state_kernel(const float* __restrict__ decay)
{
    int blk = blockIdx.x;           // bh*NC + c
    int c  = blk & (NC - 1);
    int bh = blk >> NC_SH;
    int b  = bh >> 4, h = bh & (Hh - 1);
    int tid = threadIdx.x;
    int i = tid >> 2, q = tid & 3;

    float w = expf(-expf(decay[h * Dd + i]));

    __shared__ float sk[2][TS_ST][Dd];
    __shared__ float sv[2][TS_ST][Dd];
    unsigned skb = (unsigned)__cvta_generic_to_shared(&sk[0][0][0]);
    unsigned svb = (unsigned)__cvta_generic_to_shared(&sv[0][0][0]);

    float s[16];
    #pragma unroll
    for (int j = 0; j < 16; j++) s[j] = 0.f;

    int base = (b * Tt + c * CL) * Cc + h * Dd;

    // tile loader: 32 steps * 16 float4-groups = 512 slots, 2 per thread
    #define LOAD_ST(bufi, t0) do { \
        _Pragma("unroll") \
        for (int j = 0; j < 2; j++) { \
            int idx = tid + j * 256; \
            int tl = idx >> 4, grp = (idx & 15) << 2; \
            int go = base + ((t0) + tl) * Cc + grp; \
            unsigned so = (unsigned)((((bufi) * TS_ST + tl) * Dd + grp) * 4); \
            cp_async16(skb + so, g_k + go); \
            cp_async16(svb + so, g_v + go); \
        } cp_commit(); } while (0)

    LOAD_ST(0, 0);
    for (int tile = 0; tile < CL / TS_ST; tile++) {
        cp_wait0();
        __syncthreads();
        if (tile + 1 < CL / TS_ST) LOAD_ST((tile + 1) & 1, (tile + 1) * TS_ST);
        int buf = tile & 1;
        #pragma unroll 4
        for (int tl = 0; tl < TS_ST; tl++) {
            float ki = sk[buf][tl][i];
            const float4* vv = (const float4*)&sv[buf][tl][q * 16];
            #pragma unroll
            for (int jj = 0; jj < 4; jj++) {
                float4 v4 = vv[jj];
                s[jj*4+0] = fmaf(s[jj*4+0], w, ki * v4.x);
                s[jj*4+1] = fmaf(s[jj*4+1], w, ki * v4.y);
                s[jj*4+2] = fmaf(s[jj*4+2], w, ki * v4.z);
                s[jj*4+3] = fmaf(s[jj*4+3], w, ki * v4.w);
            }
        }
    }
    #undef LOAD_ST

    float* dst = g_cs + blk * (Dd * Dd) + i * Dd + q * 16;
    #pragma unroll
    for (int jj = 0; jj < 4; jj++)
        ((float4*)dst)[jj] = make_float4(s[jj*4], s[jj*4+1], s[jj*4+2], s[jj*4+3]);
}

// ---------------- kernel 3b: prefix combine over chunks ----------------
__global__ __launch_bounds__(256) void combine_kernel(const float* __restrict__ decay)
{
    int bh = blockIdx.x;
    int h = bh & (Hh - 1);
    int tid = threadIdx.x;
    int i = tid >> 2, q = tid & 3;

    float w = expf(-expf(decay[h * Dd + i]));
    float wL = w;
    #pragma unroll
    for (int p = 0; p < 6; p++) wL *= wL;   // w^64 (CL = 64)

    float s[16];
    #pragma unroll
    for (int j = 0; j < 16; j++) s[j] = 0.f;

    for (int c = 0; c < NC; c++) {
        int off = (bh * NC + c) * (Dd * Dd) + i * Dd + q * 16;
        float4* dsti = (float4*)(g_ci + off);
        const float4* src = (const float4*)(g_cs + off);
        #pragma unroll
        for (int jj = 0; jj < 4; jj++) {
            dsti[jj] = make_float4(s[jj*4], s[jj*4+1], s[jj*4+2], s[jj*4+3]);
            float4 c4 = src[jj];
            s[jj*4+0] = fmaf(s[jj*4+0], wL, c4.x);
            s[jj*4+1] = fmaf(s[jj*4+1], wL, c4.y);
            s[jj*4+2] = fmaf(s[jj*4+2], wL, c4.z);
            s[jj*4+3] = fmaf(s[jj*4+3], wL, c4.w);
        }
    }
}

// ---------------- kernel 3c: outputs with carry-in, fused gating (tile-prefetched) ---
#define TS_OT 16
__global__ __launch_bounds__(256) void scan_out_kernel(const float* __restrict__ decay)
{
    int blk = blockIdx.x;
    int c  = blk & (NC - 1);
    int bh = blk >> NC_SH;
    int b  = bh >> 4, h = bh & (Hh - 1);
    int tid = threadIdx.x;
    int i = tid >> 2, q = tid & 3;

    float w = expf(-expf(decay[h * Dd + i]));

    // [buf][tensor 0=k,1=v,2=r,3=g][tl][d]
    __shared__ float sh[2][4][TS_OT][Dd];
    unsigned shb = (unsigned)__cvta_generic_to_shared(&sh[0][0][0][0]);

    float s[16];
    {
        const float4* src = (const float4*)(g_ci + blk * (Dd * Dd) + i * Dd + q * 16);
        #pragma unroll
        for (int jj = 0; jj < 4; jj++) {
            float4 t4 = src[jj];
            s[jj*4+0] = t4.x; s[jj*4+1] = t4.y; s[jj*4+2] = t4.z; s[jj*4+3] = t4.w;
        }
    }

    int base = (b * Tt + c * CL) * Cc + h * Dd;

    // tile loader: 4 tensors * 16 steps * 16 groups = 1024 slots, 4 per thread
    #define LOAD_OT(bufi, t0) do { \
        _Pragma("unroll") \
        for (int j = 0; j < 4; j++) { \
            int idx = tid + j * 256; \
            int tn = idx >> 8; \
            int tl = (idx >> 4) & 15; \
            int grp = (idx & 15) << 2; \
            const float* src = (tn == 0) ? g_k : (tn == 1) ? g_v : (tn == 2) ? g_r : g_g; \
            int go = base + ((t0) + tl) * Cc + grp; \
            unsigned so = (unsigned)(((((bufi) * 4 + tn) * TS_OT + tl) * Dd + grp) * 4); \
            cp_async16(shb + so, src + go); \
        } cp_commit(); } while (0)

    LOAD_OT(0, 0);
    for (int tile = 0; tile < CL / TS_OT; tile++) {
        cp_wait0();
        __syncthreads();
        if (tile + 1 < CL / TS_OT) LOAD_OT((tile + 1) & 1, (tile + 1) * TS_OT);
        int buf = tile & 1;
        #pragma unroll 2
        for (int tl = 0; tl < TS_OT; tl++) {
            float ki = sh[buf][0][tl][i];
            const float4* vv = (const float4*)&sh[buf][1][tl][q * 16];
            const float4* rr = (const float4*)&sh[buf][2][tl][q * 16];
            float a0 = 0.f, a1 = 0.f, a2 = 0.f, a3 = 0.f;
            {
                float4 v4, r4;
                v4 = vv[0]; r4 = rr[0];
                s[0] = fmaf(s[0], w, ki*v4.x); a0 = fmaf(s[0], r4.x, a0);
                s[1] = fmaf(s[1], w, ki*v4.y); a0 = fmaf(s[1], r4.y, a0);
                s[2] = fmaf(s[2], w, ki*v4.z); a0 = fmaf(s[2], r4.z, a0);
                s[3] = fmaf(s[3], w, ki*v4.w); a0 = fmaf(s[3], r4.w, a0);
                v4 = vv[1]; r4 = rr[1];
                s[4] = fmaf(s[4], w, ki*v4.x); a1 = fmaf(s[4], r4.x, a1);
                s[5] = fmaf(s[5], w, ki*v4.y); a1 = fmaf(s[5], r4.y, a1);
                s[6] = fmaf(s[6], w, ki*v4.z); a1 = fmaf(s[6], r4.z, a1);
                s[7] = fmaf(s[7], w, ki*v4.w); a1 = fmaf(s[7], r4.w, a1);
                v4 = vv[2]; r4 = rr[2];
                s[8]  = fmaf(s[8],  w, ki*v4.x); a2 = fmaf(s[8],  r4.x, a2);
                s[9]  = fmaf(s[9],  w, ki*v4.y); a2 = fmaf(s[9],  r4.y, a2);
                s[10] = fmaf(s[10], w, ki*v4.z); a2 = fmaf(s[10], r4.z, a2);
                s[11] = fmaf(s[11], w, ki*v4.w); a2 = fmaf(s[11], r4.w, a2);
                v4 = vv[3]; r4 = rr[3];
                s[12] = fmaf(s[12], w, ki*v4.x); a3 = fmaf(s[12], r4.x, a3);
                s[13] = fmaf(s[13], w, ki*v4.y); a3 = fmaf(s[13], r4.y, a3);
                s[14] = fmaf(s[14], w, ki*v4.z); a3 = fmaf(s[14], r4.z, a3);
                s[15] = fmaf(s[15], w, ki*v4.w); a3 = fmaf(s[15], r4.w, a3);
            }
            float acc = (a0 + a1) + (a2 + a3);
            acc += __shfl_xor_sync(0xffffffffu, acc, 1);
            acc += __shfl_xor_sync(0xffffffffu, acc, 2);
            if (q == 0)
                g_z[base + (tile * TS_OT + tl) * Cc + i] = tf32r(acc * sh[buf][3][tl][i]);
        }
    }
    #undef LOAD_OT
}

// ---------------- kernel 4: LayerNorm ----------------
__global__ __launch_bounds__(256) void ln_kernel(
    const float* __restrict__ gamma, const float* __restrict__ beta,
    float* __restrict__ out)
{
    int row = blockIdx.x;
    int tid = threadIdx.x;
    const float4* yr = (const float4*)(g_y + (size_t)row * Cc);
    float4 v = yr[tid];
    float sum = v.x + v.y + v.z + v.w;
    float sq  = v.x*v.x + v.y*v.y + v.z*v.z + v.w*v.w;
    #pragma unroll
    for (int o = 16; o; o >>= 1) {
        sum += __shfl_xor_sync(0xffffffffu, sum, o);
        sq  += __shfl_xor_sync(0xffffffffu, sq,  o);
    }
    __shared__ float ssum[8], ssq[8];
    int wid = tid >> 5, lid = tid & 31;
    if (lid == 0) { ssum[wid] = sum; ssq[wid] = sq; }
    __syncthreads();
    if (tid == 0) {
        float S = 0.f, Q = 0.f;
        #pragma unroll
        for (int k = 0; k < 8; k++) { S += ssum[k]; Q += ssq[k]; }
        ssum[0] = S; ssq[0] = Q;
    }
    __syncthreads();
    float mu  = ssum[0] * (1.f / Cc);
    float var = ssq[0] * (1.f / Cc) - mu * mu;
    float rstd = rsqrtf(var + 1e-5f);
    float4 ga = ((const float4*)gamma)[tid];
    float4 be = ((const float4*)beta)[tid];
    float4 o;
    o.x = (v.x - mu) * rstd * ga.x + be.x;
    o.y = (v.y - mu) * rstd * ga.y + be.y;
    o.z = (v.z - mu) * rstd * ga.z + be.z;
    o.w = (v.w - mu) * rstd * ga.w + be.w;
    ((float4*)out)[(size_t)row * (Cc / 4) + tid] = o;
}

// ---------------- launch ----------------
extern "C" void kernel_launch(void* const* d_in, const int* in_sizes, int n_in,
                              void* d_out, int out_size)
{
    const float* x   = (const float*)d_in[0];
    const float* dec = (const float*)d_in[1];
    const float* mk  = (const float*)d_in[2];
    const float* mv  = (const float*)d_in[3];
    const float* mr  = (const float*)d_in[4];
    const float* mg  = (const float*)d_in[5];
    const float* Wr  = (const float*)d_in[6];
    const float* Wk  = (const float*)d_in[7];
    const float* Wv  = (const float*)d_in[8];
    const float* Wg  = (const float*)d_in[9];
    const float* Wo  = (const float*)d_in[10];
    const float* ga  = (const float*)d_in[11];
    const float* be  = (const float*)d_in[12];
    float* out = (float*)d_out;

    float *xk, *xv, *xr, *xg, *pr, *pk, *pv, *pg, *pz, *py, *wt;
    cudaGetSymbolAddress((void**)&xk, g_xk);
    cudaGetSymbolAddress((void**)&xv, g_xv);
    cudaGetSymbolAddress((void**)&xr, g_xr);
    cudaGetSymbolAddress((void**)&xg, g_xg);
    cudaGetSymbolAddress((void**)&pr, g_r);
    cudaGetSymbolAddress((void**)&pk, g_k);
    cudaGetSymbolAddress((void**)&pv, g_v);
    cudaGetSymbolAddress((void**)&pg, g_g);
    cudaGetSymbolAddress((void**)&pz, g_z);
    cudaGetSymbolAddress((void**)&py, g_y);
    cudaGetSymbolAddress((void**)&wt, g_wt);

    // opt-in dynamic smem for the GEMM (no allocation; idempotent)
    cudaFuncSetAttribute(gemm_tf32<false>, cudaFuncAttributeMaxDynamicSharedMemorySize, GEMM_SMEM);
    cudaFuncSetAttribute(gemm_tf32<true>,  cudaFuncAttributeMaxDynamicSharedMemorySize, GEMM_SMEM);

    roundw_kernel<<<5 * Cc * Cc / 4 / 256, 256>>>(Wr, Wk, Wv, Wg, Wo);
    mix_kernel<<<MM * (Cc / 4) / 256, 256>>>(x, mk, mv, mr, mg);

    dim3 gg(Cc / BN, MM / BM);   // (8, 32)
    const int WSZ = Cc * Cc;
    gemm_tf32<false><<<gg, 512, GEMM_SMEM>>>(xr, wt + 0 * WSZ, pr);
    gemm_tf32<false><<<gg, 512, GEMM_SMEM>>>(xk, wt + 1 * WSZ, pk);
    gemm_tf32<false><<<gg, 512, GEMM_SMEM>>>(xv, wt + 2 * WSZ, pv);
    gemm_tf32<true ><<<gg, 512, GEMM_SMEM>>>(xg, wt + 3 * WSZ, pg);

    scan_state_kernel<<<Bb * Hh * NC, 256>>>(dec);
    combine_kernel<<<Bb * Hh, 256>>>(dec);
    scan_out_kernel<<<Bb * Hh * NC, 256>>>(dec);

    gemm_tf32<false><<<gg, 512, GEMM_SMEM>>>(pz, wt + 4 * WSZ, py);

    ln_kernel<<<MM, 256>>>(ga, be, out);
}

// round 17
// speedup vs baseline: 2.5414x; 1.4427x over previous
#include <cuda_runtime.h>
#include <cuda_fp16.h>
#include <stdint.h>
#include <math.h>

// Problem dims (fixed)
#define Bb 4
#define Tt 2048
#define Cc 1024
#define Hh 16
#define Dd 64
#define NC 32     // number of chunks
#define NC_SH 5
#define CL 64     // chunk length; NC*CL == Tt
#define MM (Bb*Tt)   // 8192 rows

// ---------------- scratch (device globals; no runtime alloc) ----------------
__device__ __half g_xk[MM*Cc];
__device__ __half g_xv[MM*Cc];
__device__ __half g_xr[MM*Cc];
__device__ __half g_xg[MM*Cc];
__device__ float  g_r [MM*Cc];
__device__ float  g_k [MM*Cc];
__device__ float  g_v [MM*Cc];
__device__ float  g_g [MM*Cc];
__device__ __half g_z [MM*Cc];   // attn * g (fp16)
__device__ float  g_y [MM*Cc];   // pre-LN output
__device__ float  g_cs[Bb*Hh*NC*Dd*Dd];  // chunk-local final states
__device__ float  g_ci[Bb*Hh*NC*Dd*Dd];  // chunk initial states (carry-in)
__device__ __half g_wt[5*Cc*Cc];         // fp16 weights (r,k,v,g,o)

__device__ __forceinline__ void cp_async16(unsigned dst, const void* src) {
    asm volatile("cp.async.ca.shared.global [%0], [%1], 16;\n" :: "r"(dst), "l"(src));
}
__device__ __forceinline__ void cp_commit() {
    asm volatile("cp.async.commit_group;\n" ::);
}
__device__ __forceinline__ void cp_wait0() {
    asm volatile("cp.async.wait_group 0;\n" ::);
}
__device__ __forceinline__ void cp_wait1() {
    asm volatile("cp.async.wait_group 1;\n" ::);
}
__device__ __forceinline__ void ldsm4(unsigned &d0, unsigned &d1, unsigned &d2, unsigned &d3,
                                      unsigned addr) {
    asm volatile("ldmatrix.sync.aligned.m8n8.x4.shared.b16 {%0,%1,%2,%3}, [%4];"
                 : "=r"(d0), "=r"(d1), "=r"(d2), "=r"(d3) : "r"(addr));
}

// ---------------- kernel 0: weights -> fp16 (RN) ----------------
__global__ __launch_bounds__(256) void roundw_kernel(
    const float* __restrict__ Wr, const float* __restrict__ Wk,
    const float* __restrict__ Wv, const float* __restrict__ Wg,
    const float* __restrict__ Wo)
{
    int idx = blockIdx.x * 256 + threadIdx.x;   // over 5*Cc*Cc/4
    const int per = Cc * Cc / 4;                 // float4 groups per weight
    int w = idx / per;
    int off = idx - w * per;
    const float* src = (w == 0) ? Wr : (w == 1) ? Wk : (w == 2) ? Wv : (w == 3) ? Wg : Wo;
    float4 v = ((const float4*)src)[off];
    __half2* dst = (__half2*)g_wt;
    dst[idx*2+0] = __floats2half2_rn(v.x, v.y);
    dst[idx*2+1] = __floats2half2_rn(v.z, v.w);
}

// ---------------- kernel 1: token shift + time mix (fp16 out) ----------------
__global__ __launch_bounds__(256) void mix_kernel(
    const float* __restrict__ x,
    const float* __restrict__ mk, const float* __restrict__ mv,
    const float* __restrict__ mr, const float* __restrict__ mg)
{
    const int C4 = Cc / 4;
    int idx = blockIdx.x * 256 + threadIdx.x;       // over MM * C4
    int c4  = idx & (C4 - 1);
    int bt  = idx >> 8;                              // C4 == 256
    int t   = bt & (Tt - 1);
    int ts  = (t == 0) ? 1 : t - 1;
    int sidx = (bt + (ts - t)) * C4 + c4;

    const float4* x4 = (const float4*)x;
    float4 xc = x4[idx];
    float4 xs = x4[sidx];
    float4 xx = make_float4(xs.x - xc.x, xs.y - xc.y, xs.z - xc.z, xs.w - xc.w);

    float4 m;
    m = ((const float4*)mk)[c4];
    ((__half2*)g_xk)[idx*2+0] = __floats2half2_rn(xc.x + xx.x*m.x, xc.y + xx.y*m.y);
    ((__half2*)g_xk)[idx*2+1] = __floats2half2_rn(xc.z + xx.z*m.z, xc.w + xx.w*m.w);
    m = ((const float4*)mv)[c4];
    ((__half2*)g_xv)[idx*2+0] = __floats2half2_rn(xc.x + xx.x*m.x, xc.y + xx.y*m.y);
    ((__half2*)g_xv)[idx*2+1] = __floats2half2_rn(xc.z + xx.z*m.z, xc.w + xx.w*m.w);
    m = ((const float4*)mr)[c4];
    ((__half2*)g_xr)[idx*2+0] = __floats2half2_rn(xc.x + xx.x*m.x, xc.y + xx.y*m.y);
    ((__half2*)g_xr)[idx*2+1] = __floats2half2_rn(xc.z + xx.z*m.z, xc.w + xx.w*m.w);
    m = ((const float4*)mg)[c4];
    ((__half2*)g_xg)[idx*2+0] = __floats2half2_rn(xc.x + xx.x*m.x, xc.y + xx.y*m.y);
    ((__half2*)g_xg)[idx*2+1] = __floats2half2_rn(xc.z + xx.z*m.z, xc.w + xx.w*m.w);
}

// ---------------- kernel 2: FP16 tensor-core GEMM (ldmatrix + 3-stage cp.async) ----------
// C[M,N] = A[M,K] * B[N,K]^T, both K-contiguous fp16, fp32 accumulate.
// 128x256 block tile, BK=32 halves, 256 threads (8 warps, 2 m x 4 n), warp tile 64x64.
#define BM 128
#define BN 256
#define BKH 32                      // K halves per stage chunk (64B/row)
#define ROWB 80                     // smem row stride bytes (40 halves; conflict-free LDSM)
#define NT (Cc / BKH)               // 32
#define NSTAGE 3
#define ASTG (BM * ROWB)            // 10240 bytes per stage
#define BSTG (BN * ROWB)            // 20480 bytes per stage
#define GEMM_SMEM (NSTAGE * (ASTG + BSTG))   // 92160

#define TCLOAD(kc, st) do { \
    size_t kof = (size_t)(kc) * BKH; \
    _Pragma("unroll") \
    for (int j = 0; j < 2; j++) { \
        int idx = tid + j * 256; \
        int row = idx >> 2, ch = idx & 3; \
        cp_async16(sA + (unsigned)(st) * ASTG + (unsigned)(row * ROWB + ch * 16), \
                   A + (size_t)(bm + row) * Cc + kof + ch * 8); \
    } \
    _Pragma("unroll") \
    for (int j = 0; j < 4; j++) { \
        int idx = tid + j * 256; \
        int row = idx >> 2, ch = idx & 3; \
        cp_async16(sB + (unsigned)(st) * BSTG + (unsigned)(row * ROWB + ch * 16), \
                   Bw + (size_t)(bn + row) * Cc + kof + ch * 8); \
    } \
    cp_commit(); } while (0)

template<bool SIGMOID>
__global__ __launch_bounds__(256, 1) void gemm_f16(
    const __half* __restrict__ A, const __half* __restrict__ Bw,
    float* __restrict__ Cout)
{
    extern __shared__ __align__(128) unsigned char dsm_raw[];

    const int N = Cc;
    int tid = threadIdx.x;
    int bm = blockIdx.y * BM;
    int bn = blockIdx.x * BN;

    unsigned sA;
    asm("{ .reg .u64 t; cvta.to.shared.u64 t, %1; cvt.u32.u64 %0, t; }"
        : "=r"(sA) : "l"(dsm_raw));
    unsigned sB = sA + NSTAGE * ASTG;

    int warp = tid >> 5, lane = tid & 31;
    int wm = (warp & 1) * 64;   // warp m offset
    int wn = (warp >> 1) * 64;  // warp n offset

    // ldmatrix per-thread addresses (byte offsets inside one stage)
    int lane7 = lane & 7;
    int aRow = lane7 + ((lane >> 3) & 1) * 8;   // 0..15 within 16-row mt tile
    int aColB = ((lane >> 4) & 1) * 16;         // 0 or 16 bytes (k offset, 8 halves)
    int bRow = lane7 + ((lane >> 4) & 1) * 8;   // 0..15 within 16-row nt pair
    int bColB = ((lane >> 3) & 1) * 16;
    unsigned aAddr = sA + (unsigned)((wm + aRow) * ROWB + aColB);
    unsigned bAddr = sB + (unsigned)((wn + bRow) * ROWB + bColB);

    float acc[4][8][4];
    #pragma unroll
    for (int i = 0; i < 4; i++)
        #pragma unroll
        for (int j = 0; j < 8; j++)
            #pragma unroll
            for (int r = 0; r < 4; r++) acc[i][j][r] = 0.f;

    // prologue: stages 0 and 1
    TCLOAD(0, 0);
    TCLOAD(1, 1);

    int s = 0;
    for (int t = 0; t < NT; t++) {
        if (t == NT - 1) cp_wait0(); else cp_wait1();
        __syncthreads();

        if (t + 2 < NT) {
            int sp = (s == 0) ? 2 : s - 1;          // (t+2) % 3
            TCLOAD(t + 2, sp);
        }

        unsigned aS = aAddr + (unsigned)(s * ASTG);
        unsigned bS = bAddr + (unsigned)(s * BSTG);

        #pragma unroll
        for (int kk = 0; kk < 2; kk++) {            // two k16 steps per 32-half chunk
            unsigned afr[4][4];
            unsigned bfr[8][2];
            #pragma unroll
            for (int mt = 0; mt < 4; mt++)
                ldsm4(afr[mt][0], afr[mt][1], afr[mt][2], afr[mt][3],
                      aS + (unsigned)(mt * 16 * ROWB + kk * 32));
            #pragma unroll
            for (int p = 0; p < 4; p++)
                ldsm4(bfr[2*p][0], bfr[2*p][1], bfr[2*p+1][0], bfr[2*p+1][1],
                      bS + (unsigned)(p * 16 * ROWB + kk * 32));
            #pragma unroll
            for (int mt = 0; mt < 4; mt++)
                #pragma unroll
                for (int nt = 0; nt < 8; nt++) {
                    asm volatile(
                        "mma.sync.aligned.m16n8k16.row.col.f32.f16.f16.f32 "
                        "{%0,%1,%2,%3}, {%4,%5,%6,%7}, {%8,%9}, {%0,%1,%2,%3};"
                        : "+f"(acc[mt][nt][0]), "+f"(acc[mt][nt][1]),
                          "+f"(acc[mt][nt][2]), "+f"(acc[mt][nt][3])
                        : "r"(afr[mt][0]), "r"(afr[mt][1]), "r"(afr[mt][2]), "r"(afr[mt][3]),
                          "r"(bfr[nt][0]), "r"(bfr[nt][1]));
                }
        }
        s = (s == 2) ? 0 : s + 1;
    }

    // epilogue: c0/c1 at (row=group, col=2*tg), c2/c3 at (row+8, col)
    int group = lane >> 2;
    int tg = lane & 3;
    #pragma unroll
    for (int mt = 0; mt < 4; mt++) {
        int row0 = bm + wm + mt * 16 + group;
        #pragma unroll
        for (int nt = 0; nt < 8; nt++) {
            int col = bn + wn + nt * 8 + 2 * tg;
            float v0 = acc[mt][nt][0], v1 = acc[mt][nt][1];
            float v2 = acc[mt][nt][2], v3 = acc[mt][nt][3];
            if (SIGMOID) {
                v0 = 1.f / (1.f + expf(-v0));
                v1 = 1.f / (1.f + expf(-v1));
                v2 = 1.f / (1.f + expf(-v2));
                v3 = 1.f / (1.f + expf(-v3));
            }
            *(float2*)(Cout + (size_t)row0 * N + col)       = make_float2(v0, v1);
            *(float2*)(Cout + (size_t)(row0 + 8) * N + col) = make_float2(v2, v3);
        }
    }
}

// ---------------- kernel 3a: chunk-local states (tile-prefetched) ----------------
#define TS_ST 32
__global__ __launch_bounds__(256) void scan_state_kernel(const float* __restrict__ decay)
{
    int blk = blockIdx.x;           // bh*NC + c
    int c  = blk & (NC - 1);
    int bh = blk >> NC_SH;
    int b  = bh >> 4, h = bh & (Hh - 1);
    int tid = threadIdx.x;
    int i = tid >> 2, q = tid & 3;

    float w = expf(-expf(decay[h * Dd + i]));

    __shared__ float sk[2][TS_ST][Dd];
    __shared__ float sv[2][TS_ST][Dd];
    unsigned skb, svb;
    asm("{ .reg .u64 t; cvta.to.shared.u64 t, %1; cvt.u32.u64 %0, t; }" : "=r"(skb) : "l"(&sk[0][0][0]));
    asm("{ .reg .u64 t; cvta.to.shared.u64 t, %1; cvt.u32.u64 %0, t; }" : "=r"(svb) : "l"(&sv[0][0][0]));

    float s[16];
    #pragma unroll
    for (int j = 0; j < 16; j++) s[j] = 0.f;

    int base = (b * Tt + c * CL) * Cc + h * Dd;

    #define LOAD_ST(bufi, t0) do { \
        _Pragma("unroll") \
        for (int j = 0; j < 2; j++) { \
            int idx = tid + j * 256; \
            int tl = idx >> 4, grp = (idx & 15) << 2; \
            int go = base + ((t0) + tl) * Cc + grp; \
            unsigned so = (unsigned)((((bufi) * TS_ST + tl) * Dd + grp) * 4); \
            cp_async16(skb + so, g_k + go); \
            cp_async16(svb + so, g_v + go); \
        } cp_commit(); } while (0)

    LOAD_ST(0, 0);
    for (int tile = 0; tile < CL / TS_ST; tile++) {
        cp_wait0();
        __syncthreads();
        if (tile + 1 < CL / TS_ST) LOAD_ST((tile + 1) & 1, (tile + 1) * TS_ST);
        int buf = tile & 1;
        #pragma unroll 4
        for (int tl = 0; tl < TS_ST; tl++) {
            float ki = sk[buf][tl][i];
            const float4* vv = (const float4*)&sv[buf][tl][q * 16];
            #pragma unroll
            for (int jj = 0; jj < 4; jj++) {
                float4 v4 = vv[jj];
                s[jj*4+0] = fmaf(s[jj*4+0], w, ki * v4.x);
                s[jj*4+1] = fmaf(s[jj*4+1], w, ki * v4.y);
                s[jj*4+2] = fmaf(s[jj*4+2], w, ki * v4.z);
                s[jj*4+3] = fmaf(s[jj*4+3], w, ki * v4.w);
            }
        }
    }
    #undef LOAD_ST

    float* dst = g_cs + blk * (Dd * Dd) + i * Dd + q * 16;
    #pragma unroll
    for (int jj = 0; jj < 4; jj++)
        ((float4*)dst)[jj] = make_float4(s[jj*4], s[jj*4+1], s[jj*4+2], s[jj*4+3]);
}

// ---------------- kernel 3b: prefix combine over chunks ----------------
__global__ __launch_bounds__(256) void combine_kernel(const float* __restrict__ decay)
{
    int bh = blockIdx.x;
    int h = bh & (Hh - 1);
    int tid = threadIdx.x;
    int i = tid >> 2, q = tid & 3;

    float w = expf(-expf(decay[h * Dd + i]));
    float wL = w;
    #pragma unroll
    for (int p = 0; p < 6; p++) wL *= wL;   // w^64 (CL = 64)

    float s[16];
    #pragma unroll
    for (int j = 0; j < 16; j++) s[j] = 0.f;

    for (int c = 0; c < NC; c++) {
        int off = (bh * NC + c) * (Dd * Dd) + i * Dd + q * 16;
        float4* dsti = (float4*)(g_ci + off);
        const float4* src = (const float4*)(g_cs + off);
        #pragma unroll
        for (int jj = 0; jj < 4; jj++) {
            dsti[jj] = make_float4(s[jj*4], s[jj*4+1], s[jj*4+2], s[jj*4+3]);
            float4 c4 = src[jj];
            s[jj*4+0] = fmaf(s[jj*4+0], wL, c4.x);
            s[jj*4+1] = fmaf(s[jj*4+1], wL, c4.y);
            s[jj*4+2] = fmaf(s[jj*4+2], wL, c4.z);
            s[jj*4+3] = fmaf(s[jj*4+3], wL, c4.w);
        }
    }
}

// ---------------- kernel 3c: outputs with carry-in, fused gating (tile-prefetched) ---
#define TS_OT 16
__global__ __launch_bounds__(256) void scan_out_kernel(const float* __restrict__ decay)
{
    int blk = blockIdx.x;
    int c  = blk & (NC - 1);
    int bh = blk >> NC_SH;
    int b  = bh >> 4, h = bh & (Hh - 1);
    int tid = threadIdx.x;
    int i = tid >> 2, q = tid & 3;

    float w = expf(-expf(decay[h * Dd + i]));

    // [buf][tensor 0=k,1=v,2=r,3=g][tl][d]
    __shared__ float sh[2][4][TS_OT][Dd];
    unsigned shb;
    asm("{ .reg .u64 t; cvta.to.shared.u64 t, %1; cvt.u32.u64 %0, t; }" : "=r"(shb) : "l"(&sh[0][0][0][0]));

    float s[16];
    {
        const float4* src = (const float4*)(g_ci + blk * (Dd * Dd) + i * Dd + q * 16);
        #pragma unroll
        for (int jj = 0; jj < 4; jj++) {
            float4 t4 = src[jj];
            s[jj*4+0] = t4.x; s[jj*4+1] = t4.y; s[jj*4+2] = t4.z; s[jj*4+3] = t4.w;
        }
    }

    int base = (b * Tt + c * CL) * Cc + h * Dd;

    #define LOAD_OT(bufi, t0) do { \
        _Pragma("unroll") \
        for (int j = 0; j < 4; j++) { \
            int idx = tid + j * 256; \
            int tn = idx >> 8; \
            int tl = (idx >> 4) & 15; \
            int grp = (idx & 15) << 2; \
            const float* src = (tn == 0) ? g_k : (tn == 1) ? g_v : (tn == 2) ? g_r : g_g; \
            int go = base + ((t0) + tl) * Cc + grp; \
            unsigned so = (unsigned)(((((bufi) * 4 + tn) * TS_OT + tl) * Dd + grp) * 4); \
            cp_async16(shb + so, src + go); \
        } cp_commit(); } while (0)

    LOAD_OT(0, 0);
    for (int tile = 0; tile < CL / TS_OT; tile++) {
        cp_wait0();
        __syncthreads();
        if (tile + 1 < CL / TS_OT) LOAD_OT((tile + 1) & 1, (tile + 1) * TS_OT);
        int buf = tile & 1;
        #pragma unroll 2
        for (int tl = 0; tl < TS_OT; tl++) {
            float ki = sh[buf][0][tl][i];
            const float4* vv = (const float4*)&sh[buf][1][tl][q * 16];
            const float4* rr = (const float4*)&sh[buf][2][tl][q * 16];
            float a0 = 0.f, a1 = 0.f, a2 = 0.f, a3 = 0.f;
            {
                float4 v4, r4;
                v4 = vv[0]; r4 = rr[0];
                s[0] = fmaf(s[0], w, ki*v4.x); a0 = fmaf(s[0], r4.x, a0);
                s[1] = fmaf(s[1], w, ki*v4.y); a0 = fmaf(s[1], r4.y, a0);
                s[2] = fmaf(s[2], w, ki*v4.z); a0 = fmaf(s[2], r4.z, a0);
                s[3] = fmaf(s[3], w, ki*v4.w); a0 = fmaf(s[3], r4.w, a0);
                v4 = vv[1]; r4 = rr[1];
                s[4] = fmaf(s[4], w, ki*v4.x); a1 = fmaf(s[4], r4.x, a1);
                s[5] = fmaf(s[5], w, ki*v4.y); a1 = fmaf(s[5], r4.y, a1);
                s[6] = fmaf(s[6], w, ki*v4.z); a1 = fmaf(s[6], r4.z, a1);
                s[7] = fmaf(s[7], w, ki*v4.w); a1 = fmaf(s[7], r4.w, a1);
                v4 = vv[2]; r4 = rr[2];
                s[8]  = fmaf(s[8],  w, ki*v4.x); a2 = fmaf(s[8],  r4.x, a2);
                s[9]  = fmaf(s[9],  w, ki*v4.y); a2 = fmaf(s[9],  r4.y, a2);
                s[10] = fmaf(s[10], w, ki*v4.z); a2 = fmaf(s[10], r4.z, a2);
                s[11] = fmaf(s[11], w, ki*v4.w); a2 = fmaf(s[11], r4.w, a2);
                v4 = vv[3]; r4 = rr[3];
                s[12] = fmaf(s[12], w, ki*v4.x); a3 = fmaf(s[12], r4.x, a3);
                s[13] = fmaf(s[13], w, ki*v4.y); a3 = fmaf(s[13], r4.y, a3);
                s[14] = fmaf(s[14], w, ki*v4.z); a3 = fmaf(s[14], r4.z, a3);
                s[15] = fmaf(s[15], w, ki*v4.w); a3 = fmaf(s[15], r4.w, a3);
            }
            float acc = (a0 + a1) + (a2 + a3);
            acc += __shfl_xor_sync(0xffffffffu, acc, 1);
            acc += __shfl_xor_sync(0xffffffffu, acc, 2);
            if (q == 0)
                g_z[base + (tile * TS_OT + tl) * Cc + i] = __float2half_rn(acc * sh[buf][3][tl][i]);
        }
    }
    #undef LOAD_OT
}

// ---------------- kernel 4: LayerNorm ----------------
__global__ __launch_bounds__(256) void ln_kernel(
    const float* __restrict__ gamma, const float* __restrict__ beta,
    float* __restrict__ out)
{
    int row = blockIdx.x;
    int tid = threadIdx.x;
    const float4* yr = (const float4*)(g_y + (size_t)row * Cc);
    float4 v = yr[tid];
    float sum = v.x + v.y + v.z + v.w;
    float sq  = v.x*v.x + v.y*v.y + v.z*v.z + v.w*v.w;
    #pragma unroll
    for (int o = 16; o; o >>= 1) {
        sum += __shfl_xor_sync(0xffffffffu, sum, o);
        sq  += __shfl_xor_sync(0xffffffffu, sq,  o);
    }
    __shared__ float ssum[8], ssq[8];
    int wid = tid >> 5, lid = tid & 31;
    if (lid == 0) { ssum[wid] = sum; ssq[wid] = sq; }
    __syncthreads();
    if (tid == 0) {
        float S = 0.f, Q = 0.f;
        #pragma unroll
        for (int k = 0; k < 8; k++) { S += ssum[k]; Q += ssq[k]; }
        ssum[0] = S; ssq[0] = Q;
    }
    __syncthreads();
    float mu  = ssum[0] * (1.f / Cc);
    float var = ssq[0] * (1.f / Cc) - mu * mu;
    float rstd = rsqrtf(var + 1e-5f);
    float4 ga = ((const float4*)gamma)[tid];
    float4 be = ((const float4*)beta)[tid];
    float4 o;
    o.x = (v.x - mu) * rstd * ga.x + be.x;
    o.y = (v.y - mu) * rstd * ga.y + be.y;
    o.z = (v.z - mu) * rstd * ga.z + be.z;
    o.w = (v.w - mu) * rstd * ga.w + be.w;
    ((float4*)out)[(size_t)row * (Cc / 4) + tid] = o;
}

// ---------------- launch ----------------
extern "C" void kernel_launch(void* const* d_in, const int* in_sizes, int n_in,
                              void* d_out, int out_size)
{
    const float* x   = (const float*)d_in[0];
    const float* dec = (const float*)d_in[1];
    const float* mk  = (const float*)d_in[2];
    const float* mv  = (const float*)d_in[3];
    const float* mr  = (const float*)d_in[4];
    const float* mg  = (const float*)d_in[5];
    const float* Wr  = (const float*)d_in[6];
    const float* Wk  = (const float*)d_in[7];
    const float* Wv  = (const float*)d_in[8];
    const float* Wg  = (const float*)d_in[9];
    const float* Wo  = (const float*)d_in[10];
    const float* ga  = (const float*)d_in[11];
    const float* be  = (const float*)d_in[12];
    float* out = (float*)d_out;

    __half *xk, *xv, *xr, *xg, *pz, *wt;
    float *pr, *pk, *pv, *pg, *py;
    cudaGetSymbolAddress((void**)&xk, g_xk);
    cudaGetSymbolAddress((void**)&xv, g_xv);
    cudaGetSymbolAddress((void**)&xr, g_xr);
    cudaGetSymbolAddress((void**)&xg, g_xg);
    cudaGetSymbolAddress((void**)&pr, g_r);
    cudaGetSymbolAddress((void**)&pk, g_k);
    cudaGetSymbolAddress((void**)&pv, g_v);
    cudaGetSymbolAddress((void**)&pg, g_g);
    cudaGetSymbolAddress((void**)&pz, g_z);
    cudaGetSymbolAddress((void**)&py, g_y);
    cudaGetSymbolAddress((void**)&wt, g_wt);

    // opt-in dynamic smem for the GEMM (no allocation; idempotent)
    cudaFuncSetAttribute(gemm_f16<false>, cudaFuncAttributeMaxDynamicSharedMemorySize, GEMM_SMEM);
    cudaFuncSetAttribute(gemm_f16<true>,  cudaFuncAttributeMaxDynamicSharedMemorySize, GEMM_SMEM);

    roundw_kernel<<<5 * Cc * Cc / 4 / 256, 256>>>(Wr, Wk, Wv, Wg, Wo);
    mix_kernel<<<MM * (Cc / 4) / 256, 256>>>(x, mk, mv, mr, mg);

    dim3 gg(Cc / BN, MM / BM);   // (4, 64)
    const int WSZ = Cc * Cc;
    gemm_f16<false><<<gg, 256, GEMM_SMEM>>>(xr, wt + 0 * WSZ, pr);
    gemm_f16<false><<<gg, 256, GEMM_SMEM>>>(xk, wt + 1 * WSZ, pk);
    gemm_f16<false><<<gg, 256, GEMM_SMEM>>>(xv, wt + 2 * WSZ, pv);
    gemm_f16<true ><<<gg, 256, GEMM_SMEM>>>(xg, wt + 3 * WSZ, pg);

    scan_state_kernel<<<Bb * Hh * NC, 256>>>(dec);
    combine_kernel<<<Bb * Hh, 256>>>(dec);
    scan_out_kernel<<<Bb * Hh * NC, 256>>>(dec);

    gemm_f16<false><<<gg, 256, GEMM_SMEM>>>(pz, wt + 4 * WSZ, py);

    ln_kernel<<<MM, 256>>>(ga, be, out);
}